// round 12
// baseline (speedup 1.0000x reference)
#include <cuda_runtime.h>
#include <cuda_fp16.h>
#include <math.h>
#include <stdint.h>

// Problem constants
#define Bq   16
#define Sq   2048
#define Hq   1024
#define Nq   128
#define NROWS (Bq * Nq)
#define NPAD  (NROWS + 128)
#define KXn  4096                // [L0 | L1 | alpha*Init | Init]

// ---------------- scratch (static __device__, no allocation) ----------------
__device__ __half g_X[(size_t)NROWS * KXn];     // operand rows, original order
__device__ __half g_Wcat[2u * Hq * KXn];        // per-group weights [ri][n][4096]
__device__ float g_T[Bq][2][Hq];
__device__ float g_C[2][Bq][Hq];
__device__ float g_alpha[NROWS];
__device__ int   g_perm[NROWS];
__device__ int   g_runstart[NROWS];
__device__ float g_invD[Bq];
__device__ int   g_rowmap[NPAD];
__device__ int   g_meta[2];

// ---------------- helpers ----------------
__device__ __forceinline__ uint32_t smem_u32(const void* p) {
    uint32_t a;
    asm("{ .reg .u64 t; cvta.to.shared.u64 t, %1; cvt.u32.u64 %0, t; }" : "=r"(a) : "l"(p));
    return a;
}
#define CP16(dst, src) asm volatile("cp.async.cg.shared.global [%0], [%1], 16;" :: "r"(dst), "l"(src) : "memory")
#define CP_COMMIT()    asm volatile("cp.async.commit_group;" ::: "memory")
#define CP_WAIT2()     asm volatile("cp.async.wait_group 2;" ::: "memory")

__device__ __forceinline__ void mma_f16(float* d, const uint32_t* a, const uint32_t* b) {
    asm volatile("mma.sync.aligned.m16n8k16.row.col.f32.f16.f16.f32 "
                 "{%0,%1,%2,%3}, {%4,%5,%6,%7}, {%8,%9}, {%0,%1,%2,%3};"
                 : "+f"(d[0]), "+f"(d[1]), "+f"(d[2]), "+f"(d[3])
                 : "r"(a[0]), "r"(a[1]), "r"(a[2]), "r"(a[3]), "r"(b[0]), "r"(b[1]));
}
__device__ __forceinline__ void ldsm4(uint32_t& r0, uint32_t& r1, uint32_t& r2, uint32_t& r3,
                                      uint32_t addr) {
    asm volatile("ldmatrix.sync.aligned.m8n8.x4.shared.b16 {%0,%1,%2,%3}, [%4];"
                 : "=r"(r0), "=r"(r1), "=r"(r2), "=r"(r3) : "r"(addr));
}

// ================= K_megaA: gather+alpha | rank | group (stream 0) ===========
#define GA_RANK   2048
#define GA_GROUP  2064
#define GA_TOTAL  2065

__global__ void __launch_bounds__(256) k_megaA(
    const float* __restrict__ we, const int* __restrict__ ids,
    const float* __restrict__ w_alpha, const float* __restrict__ b_alpha,
    const float* __restrict__ numbers, const int* __restrict__ resp)
{
    int blk = blockIdx.x, tid = threadIdx.x;

    if (blk < GA_RANK) {
        // ---- gather Init row m (fp16, original order) + alpha ----
        int m = blk, b = m >> 7;
        int id = ids[m];
        int idc = min(max(id, 0), Sq - 1);
        const float4* src = (const float4*)(we + ((size_t)b * Sq + idc) * Hq);
        __half2* dst = (__half2*)(g_X + (size_t)m * KXn + 3 * Hq);
        const float4* wa = (const float4*)w_alpha;
        float4 v = src[tid];
        float4 w = wa[tid];
        float part = v.x * w.x + v.y * w.y + v.z * w.z + v.w * w.w;
        dst[2 * tid]     = __floats2half2_rn(v.x, v.y);
        dst[2 * tid + 1] = __floats2half2_rn(v.z, v.w);
        #pragma unroll
        for (int s = 16; s > 0; s >>= 1)
            part += __shfl_xor_sync(0xFFFFFFFFu, part, s);
        __shared__ float red[8];
        if ((tid & 31) == 0) red[tid >> 5] = part;
        __syncthreads();
        if (tid == 0) {
            float t = 0.f;
            #pragma unroll
            for (int q = 0; q < 8; q++) t += red[q];
            float a = 1.f / (1.f + expf(-(t + b_alpha[0])));
            g_alpha[m] = (id >= 0) ? a : 0.f;
        }
    } else if (blk < GA_GROUP) {
        // ---- rank (per batch b) ----
        int b = blk - GA_RANK;
        int i = tid;
        __shared__ float num[128];
        __shared__ int perm[128];
        __shared__ int validCnt;
        int id = 0; float x = 0.f;
        if (i < 128) {
            id = ids[b * 128 + i];
            x = numbers[b * 128 + i];
            num[i] = x;
        }
        if (i == 0) validCnt = 0;
        __syncthreads();
        if (i < 128) {
            int p = 0;
            #pragma unroll 4
            for (int j = 0; j < 128; j++) {
                float y = num[j];
                p += (y < x) || (y == x && j < i);
            }
            perm[p] = i;
            atomicAdd(&validCnt, (id >= 0) ? 1 : 0);
        }
        __syncthreads();
        if (i < 128) {
            g_perm[b * 128 + i] = perm[i];
            int node = perm[i];
            int prev = (i > 0) ? perm[i - 1] : 0;
            g_runstart[b * 128 + i] = (i == 0) || (num[node] != num[prev]);
        }
        if (i == 0) g_invD[b] = 1.f / (float)max(validCnt - 1, 1);
    } else {
        // ---- group rows by resp_i (parallel scan) ----
        __shared__ int cls[NROWS];
        __shared__ int sc[256];
        __shared__ int tcount[256];
        int t = tid;
        for (int m = t; m < NROWS; m += 256) cls[m] = (resp[m] == 1) ? 1 : 0;
        __syncthreads();
        int c0 = 0;
        #pragma unroll
        for (int k = 0; k < 8; k++) c0 += (cls[t * 8 + k] == 0);
        tcount[t] = c0;
        sc[t] = c0;
        __syncthreads();
        #pragma unroll
        for (int step = 1; step < 256; step <<= 1) {
            int v = (t >= step) ? sc[t - step] : 0;
            __syncthreads();
            sc[t] += v;
            __syncthreads();
        }
        int count0 = sc[255];
        int off0 = sc[t] - tcount[t];
        int start1 = ((count0 + 127) / 128) * 128;
        int total1 = NROWS - count0;
        int totalTiles = (start1 + total1 + 127) / 128;
        for (int m = t; m < NPAD; m += 256) g_rowmap[m] = -1;
        __syncthreads();
        int p0 = off0;
        int p1 = start1 + (t * 8 - off0);
        #pragma unroll
        for (int k = 0; k < 8; k++) {
            int m = t * 8 + k;
            if (cls[m] == 0) { g_rowmap[p0] = m; p0++; }
            else             { g_rowmap[p1] = m; p1++; }
        }
        if (t == 0) { g_meta[0] = start1; g_meta[1] = totalTiles; }
    }
}

// ================= K_megaB: wprep | transpose (stream 2, overlapped) =========
#define GBB_TRANS 2048
#define GBB_TOTAL 3072

__global__ void __launch_bounds__(256) k_megaB(
    const float* __restrict__ Wr, const float* __restrict__ wf)
{
    int blk = blockIdx.x, tid = threadIdx.x;

    if (blk < GBB_TRANS) {
        // ---- wprep: slots 0..2 of Wcat ----
        int idx = blk;
        int ri = idx >> 10, n = idx & 1023;
        int k = tid * 4;
        const float4 a = *(const float4*)(Wr + (size_t)(4 + 2 * ri) * Hq * Hq + (size_t)n * Hq + k);
        const float4 c = *(const float4*)(Wr + (size_t)(2 * ri)     * Hq * Hq + (size_t)n * Hq + k);
        const float4 b = *(const float4*)(Wr + (size_t)(5 + 2 * ri) * Hq * Hq + (size_t)n * Hq + k);
        const float4 d = *(const float4*)(Wr + (size_t)(2 * ri + 1) * Hq * Hq + (size_t)n * Hq + k);
        const float4 e = *(const float4*)(Wr + (size_t)(3 * ri)     * Hq * Hq + (size_t)n * Hq + k);
        __half* dstw = g_Wcat + (size_t)ri * Hq * KXn + (size_t)n * KXn;
        __half2* d0 = (__half2*)(dstw + k);
        __half2* d1 = (__half2*)(dstw + Hq + k);
        __half2* d2 = (__half2*)(dstw + 2 * Hq + k);
        d0[0] = __floats2half2_rn(a.x - c.x, a.y - c.y);
        d0[1] = __floats2half2_rn(a.z - c.z, a.w - c.w);
        d1[0] = __floats2half2_rn(b.x - d.x, b.y - d.y);
        d1[1] = __floats2half2_rn(b.z - d.z, b.w - d.w);
        d2[0] = __floats2half2_rn(-e.x, -e.y);
        d2[1] = __floats2half2_rn(-e.z, -e.w);
    } else {
        // ---- transpose w_f -> Wcat slot3 (both groups) ----
        int idx = blk - GBB_TRANS;
        int x0 = (idx & 31) * 32, y0 = (idx >> 5) * 32;
        int tx = tid & 31, ty = tid >> 5;
        __shared__ float t[32][33];
        #pragma unroll
        for (int r = 0; r < 32; r += 8)
            t[ty + r][tx] = wf[(size_t)(y0 + ty + r) * Hq + x0 + tx];
        __syncthreads();
        #pragma unroll
        for (int r = 0; r < 32; r += 8) {
            int n = x0 + ty + r, h = y0 + tx;
            __half v = __float2half_rn(t[tx][ty + r]);
            g_Wcat[(size_t)n * KXn + 3 * Hq + h] = v;
            g_Wcat[(size_t)Hq * KXn + (size_t)n * KXn + 3 * Hq + h] = v;
        }
    }
}

// ---------- K_prefix: prefix sums via smem cache (grid (16,8), 128 thr) ------
__global__ void __launch_bounds__(128) k_prefix(const int* __restrict__ resp) {
    int b = blockIdx.x, tid = threadIdx.x;
    int h = blockIdx.y * 128 + tid;
    extern __shared__ float u[];                 // [128 i][128 h]
    __shared__ float alpha_s[128];
    __shared__ int perm_s[128], rs_s[128], resp_s[128];
    alpha_s[tid] = g_alpha[b * 128 + tid];
    perm_s[tid]  = g_perm[b * 128 + tid];
    rs_s[tid]    = g_runstart[b * 128 + tid];
    resp_s[tid]  = resp[b * 128 + tid];
    __syncthreads();
    #pragma unroll 8
    for (int i = 0; i < 128; i++)
        u[i * 128 + tid] = alpha_s[i] *
            __half2float(g_X[(size_t)(b * 128 + i) * KXn + 3 * Hq + h]);
    __syncthreads();
    float T0 = 0.f, T1 = 0.f;
    #pragma unroll 8
    for (int i = 0; i < 128; i++) {
        float uu = u[i * 128 + tid];
        if (resp_s[i]) T1 += uu; else T0 += uu;
    }
    g_T[b][0][h] = T0;
    g_T[b][1][h] = T1;
    float invD = g_invD[b];
    float a0 = 0.f, a1 = 0.f, s0 = 0.f, s1 = 0.f;
    for (int p = 0; p < 128; p++) {
        int i = perm_s[p];
        if (rs_s[p]) { s0 = a0; s1 = a1; }
        float uu = u[i * 128 + tid];
        __half* Xi = g_X + (size_t)(b * 128 + i) * KXn;
        Xi[h]          = __float2half_rn(s0 * invD);
        Xi[Hq + h]     = __float2half_rn(s1 * invD);
        Xi[2 * Hq + h] = __float2half_rn(uu * invD);
        if (resp_s[i]) a1 += uu; else a0 += uu;
    }
}

// ---------- Kc: per-(ri,b) constant C = invD*(W2r*T0 + W2r+1*T1) + b_f ------
__global__ void k_const(const float* __restrict__ Wr, const float* __restrict__ b_f) {
    int wg = blockIdx.x * 8 + (threadIdx.x >> 5);
    int lane = threadIdx.x & 31;
    int ri = wg >> 10, h = wg & 1023;
    const float* w0 = Wr + (size_t)(2 * ri)     * Hq * Hq + (size_t)h * Hq;
    const float* w1 = Wr + (size_t)(2 * ri + 1) * Hq * Hq + (size_t)h * Hq;
    float acc[16];
    #pragma unroll
    for (int b = 0; b < 16; b++) acc[b] = 0.f;
    for (int kb = 0; kb < Hq; kb += 32) {
        int k = kb + lane;
        float a0 = w0[k], a1 = w1[k];
        #pragma unroll
        for (int b = 0; b < 16; b++)
            acc[b] += a0 * g_T[b][0][k] + a1 * g_T[b][1][k];
    }
    #pragma unroll
    for (int b = 0; b < 16; b++)
        #pragma unroll
        for (int s = 16; s > 0; s >>= 1)
            acc[b] += __shfl_xor_sync(0xFFFFFFFFu, acc[b], s);
    if (lane == 0) {
        float bf = b_f[h];
        #pragma unroll
        for (int b = 0; b < 16; b++)
            g_C[ri][b][h] = acc[b] * g_invD[b] + bf;
    }
}

// ---------------- K5: fp16 mma GEMM (R10 config: BN=128, 4-stage) ------------
#define BK      64
#define NKT     (KXn / BK)       // 64
#define TILE_B  (128 * 128)      // bytes per operand tile

__global__ void __launch_bounds__(256, 1)
k_gemm(float* __restrict__ out) {
    int by = blockIdx.y, bx = blockIdx.x;
    if (by >= g_meta[1]) return;

    extern __shared__ char smc[];
    char* As = smc;                      // [4][TILE_B]
    char* Bs = smc + 4 * TILE_B;
    int* rows_s = (int*)(smc + 8 * TILE_B);

    int tid = threadIdx.x;
    int wid = tid >> 5, lane = tid & 31;
    int g = lane >> 2, t4 = lane & 3;
    int wm = wid & 3, wn = wid >> 2;

    for (int r = tid; r < 128; r += 256) rows_s[r] = g_rowmap[by * 128 + r];
    __syncthreads();

    int ri = (by * 128 >= g_meta[0]) ? 1 : 0;
    const __half* Bbase = g_Wcat + (size_t)ri * Hq * KXn + (size_t)(bx * 128) * KXn;
    const float* Cp = &g_C[ri][0][0];

    int cr[4], cch[4], dsw[4];
    const __half* Asrc[4];
    #pragma unroll
    for (int i = 0; i < 4; i++) {
        int idx = tid + i * 256;
        cr[i] = idx >> 3;
        int chunk = idx & 7;
        cch[i] = chunk * 8;
        dsw[i] = cr[i] * 128 + ((chunk ^ (cr[i] & 7)) << 4);
        int grow = rows_s[cr[i]];
        if (grow < 0) grow = 0;
        Asrc[i] = g_X + (size_t)grow * KXn + cch[i];
    }
    uint32_t asb = smem_u32(As), bsb = smem_u32(Bs);

    auto load_tile = [&](int kt, int slot) {
        int kk = kt * BK;
        #pragma unroll
        for (int i = 0; i < 4; i++) {
            CP16(asb + slot * TILE_B + dsw[i], Asrc[i] + kk);
            CP16(bsb + slot * TILE_B + dsw[i],
                 Bbase + (size_t)cr[i] * KXn + kk + cch[i]);
        }
    };

    int rA0 = wm * 32 + (lane & 15);
    int hiA = lane >> 4;
    int nB  = wn * 64 + (lane & 7) + ((lane >> 4) << 3);
    int hiB = (lane >> 3) & 1;

    float acc[2][8][4];
    #pragma unroll
    for (int mf = 0; mf < 2; mf++)
        #pragma unroll
        for (int nf = 0; nf < 8; nf++)
            #pragma unroll
            for (int q = 0; q < 4; q++) acc[mf][nf][q] = 0.f;

    load_tile(0, 0); CP_COMMIT();
    load_tile(1, 1); CP_COMMIT();
    load_tile(2, 2); CP_COMMIT();

    for (int kt = 0; kt < NKT; kt++) {
        int slot = kt & 3;
        CP_WAIT2();
        __syncthreads();
        if (kt + 3 < NKT) load_tile(kt + 3, (kt + 3) & 3);
        CP_COMMIT();

        uint32_t At = asb + slot * TILE_B;
        uint32_t Bt = bsb + slot * TILE_B;
        #pragma unroll
        for (int k16 = 0; k16 < 4; k16++) {
            int kc = k16 * 2;
            uint32_t a[2][4], b[8][2];
            #pragma unroll
            for (int mf = 0; mf < 2; mf++) {
                int row = rA0 + mf * 16;
                uint32_t ad = At + row * 128 + (((kc + hiA) ^ (row & 7)) << 4);
                ldsm4(a[mf][0], a[mf][1], a[mf][2], a[mf][3], ad);
            }
            #pragma unroll
            for (int np = 0; np < 4; np++) {
                int row = nB + np * 16;
                uint32_t bd = Bt + row * 128 + (((kc + hiB) ^ (row & 7)) << 4);
                ldsm4(b[2 * np][0], b[2 * np][1], b[2 * np + 1][0], b[2 * np + 1][1], bd);
            }
            #pragma unroll
            for (int mf = 0; mf < 2; mf++)
                #pragma unroll
                for (int nf = 0; nf < 8; nf++)
                    mma_f16(acc[mf][nf], a[mf], b[nf]);
        }
    }

    // ---- epilogue: + C[ri][b] (incl b_f), relu, scatter rows ----
    #pragma unroll
    for (int mf = 0; mf < 2; mf++) {
        int m0 = wm * 32 + mf * 16 + g;
        int row0 = rows_s[m0];
        int row1 = rows_s[m0 + 8];
        #pragma unroll
        for (int nf = 0; nf < 8; nf++) {
            int col = bx * 128 + wn * 64 + nf * 8 + t4 * 2;
            if (row0 >= 0) {
                const float* c0 = Cp + (size_t)(row0 >> 7) * Hq + col;
                float2 v;
                v.x = fmaxf(acc[mf][nf][0] + c0[0], 0.f);
                v.y = fmaxf(acc[mf][nf][1] + c0[1], 0.f);
                *(float2*)(out + (size_t)row0 * Hq + col) = v;
            }
            if (row1 >= 0) {
                const float* c1 = Cp + (size_t)(row1 >> 7) * Hq + col;
                float2 v;
                v.x = fmaxf(acc[mf][nf][2] + c1[0], 0.f);
                v.y = fmaxf(acc[mf][nf][3] + c1[1], 0.f);
                *(float2*)(out + (size_t)row1 * Hq + col) = v;
            }
        }
    }
}

#define SMEM_GEMM   (8 * TILE_B + 512)
#define SMEM_PREFIX (128 * 128 * 4)

// ---------------- launch: 2-stream fork/join (graph-capturable) --------------
extern "C" void kernel_launch(void* const* d_in, const int* in_sizes, int n_in,
                              void* d_out, int out_size) {
    const float* word_emb  = (const float*)d_in[0];
    const int*   num_ids   = (const int*)  d_in[1];
    const int*   is_resp   = (const int*)  d_in[2];
    const float* numbers   = (const float*)d_in[3];
    const float* w_alpha   = (const float*)d_in[4];
    const float* b_alpha   = (const float*)d_in[5];
    const float* w_f       = (const float*)d_in[6];
    const float* b_f       = (const float*)d_in[7];
    const float* W_r       = (const float*)d_in[8];
    float* out = (float*)d_out;

    static cudaStream_t s2 = nullptr;
    static cudaEvent_t eFork = nullptr, eJoin = nullptr;
    if (s2 == nullptr) {
        cudaStreamCreateWithFlags(&s2, cudaStreamNonBlocking);
        cudaEventCreateWithFlags(&eFork, cudaEventDisableTiming);
        cudaEventCreateWithFlags(&eJoin, cudaEventDisableTiming);
    }

    // fork: stream2 runs weight prep (independent of gather/prefix/const chain)
    cudaEventRecord(eFork, 0);
    cudaStreamWaitEvent(s2, eFork, 0);
    k_megaB<<<GBB_TOTAL, 256, 0, s2>>>(W_r, w_f);
    cudaEventRecord(eJoin, s2);

    // main chain on default stream
    k_megaA<<<GA_TOTAL, 256>>>(word_emb, num_ids, w_alpha, b_alpha, numbers, is_resp);

    cudaFuncSetAttribute(k_prefix, cudaFuncAttributeMaxDynamicSharedMemorySize, SMEM_PREFIX);
    k_prefix<<<dim3(Bq, 8), 128, SMEM_PREFIX>>>(is_resp);

    k_const<<<256, 256>>>(W_r, b_f);

    // join: gemm needs Wcat from stream2
    cudaStreamWaitEvent(0, eJoin, 0);

    cudaFuncSetAttribute(k_gemm, cudaFuncAttributeMaxDynamicSharedMemorySize, SMEM_GEMM);
    k_gemm<<<dim3(8, 17), 256, SMEM_GEMM>>>(out);
}

// round 13
// speedup vs baseline: 1.4610x; 1.4610x over previous
#include <cuda_runtime.h>
#include <cuda_fp16.h>
#include <math.h>
#include <stdint.h>

// Problem constants
#define Bq   16
#define Sq   2048
#define Hq   1024
#define Nq   128
#define NROWS (Bq * Nq)
#define NPAD  (NROWS + 128)
#define KXn  4096                // [L0 | L1 | alpha*Init | Init]

// ---------------- scratch (static __device__, no allocation) ----------------
__device__ __half g_X[(size_t)NROWS * KXn];     // operand rows, original order
__device__ __half g_Wcat[2u * Hq * KXn];        // per-group weights [ri][n][4096]
__device__ float g_T[Bq][2][Hq];
__device__ float g_C[2][Bq][Hq];
__device__ float g_alpha[NROWS];
__device__ int   g_perm[NROWS];
__device__ int   g_runstart[NROWS];
__device__ float g_invD[Bq];
__device__ int   g_rowmap[NPAD];
__device__ int   g_meta[2];

// ---------------- helpers ----------------
__device__ __forceinline__ uint32_t smem_u32(const void* p) {
    uint32_t a;
    asm("{ .reg .u64 t; cvta.to.shared.u64 t, %1; cvt.u32.u64 %0, t; }" : "=r"(a) : "l"(p));
    return a;
}
#define CP16(dst, src) asm volatile("cp.async.cg.shared.global [%0], [%1], 16;" :: "r"(dst), "l"(src) : "memory")
#define CP_COMMIT()    asm volatile("cp.async.commit_group;" ::: "memory")
#define CP_WAIT2()     asm volatile("cp.async.wait_group 2;" ::: "memory")

__device__ __forceinline__ void mma_f16(float* d, const uint32_t* a, const uint32_t* b) {
    asm volatile("mma.sync.aligned.m16n8k16.row.col.f32.f16.f16.f32 "
                 "{%0,%1,%2,%3}, {%4,%5,%6,%7}, {%8,%9}, {%0,%1,%2,%3};"
                 : "+f"(d[0]), "+f"(d[1]), "+f"(d[2]), "+f"(d[3])
                 : "r"(a[0]), "r"(a[1]), "r"(a[2]), "r"(a[3]), "r"(b[0]), "r"(b[1]));
}
__device__ __forceinline__ void ldsm4(uint32_t& r0, uint32_t& r1, uint32_t& r2, uint32_t& r3,
                                      uint32_t addr) {
    asm volatile("ldmatrix.sync.aligned.m8n8.x4.shared.b16 {%0,%1,%2,%3}, [%4];"
                 : "=r"(r0), "=r"(r1), "=r"(r2), "=r"(r3) : "r"(addr));
}

// ================= K_mega: all independent prep, one launch ==================
#define GB_WPREP  2048
#define GB_TRANS  4096
#define GB_RANK   5120
#define GB_GROUP  5136
#define GB_TOTAL  5137

__global__ void __launch_bounds__(256) k_mega(
    const float* __restrict__ we, const int* __restrict__ ids,
    const float* __restrict__ w_alpha, const float* __restrict__ b_alpha,
    const float* __restrict__ wf, const float* __restrict__ Wr,
    const float* __restrict__ numbers, const int* __restrict__ resp)
{
    int blk = blockIdx.x, tid = threadIdx.x;

    if (blk < GB_WPREP) {
        // ---- gather Init row m (fp16, original order) + alpha ----
        int m = blk, b = m >> 7;
        int id = ids[m];
        int idc = min(max(id, 0), Sq - 1);
        const float4* src = (const float4*)(we + ((size_t)b * Sq + idc) * Hq);
        __half2* dst = (__half2*)(g_X + (size_t)m * KXn + 3 * Hq);
        const float4* wa = (const float4*)w_alpha;
        float4 v = src[tid];
        float4 w = wa[tid];
        float part = v.x * w.x + v.y * w.y + v.z * w.z + v.w * w.w;
        dst[2 * tid]     = __floats2half2_rn(v.x, v.y);
        dst[2 * tid + 1] = __floats2half2_rn(v.z, v.w);
        #pragma unroll
        for (int s = 16; s > 0; s >>= 1)
            part += __shfl_xor_sync(0xFFFFFFFFu, part, s);
        __shared__ float red[8];
        if ((tid & 31) == 0) red[tid >> 5] = part;
        __syncthreads();
        if (tid == 0) {
            float t = 0.f;
            #pragma unroll
            for (int q = 0; q < 8; q++) t += red[q];
            float a = 1.f / (1.f + expf(-(t + b_alpha[0])));
            g_alpha[m] = (id >= 0) ? a : 0.f;
        }
    } else if (blk < GB_TRANS) {
        // ---- wprep: slots 0..2 of Wcat ----
        int idx = blk - GB_WPREP;
        int ri = idx >> 10, n = idx & 1023;
        int k = tid * 4;
        const float4 a = *(const float4*)(Wr + (size_t)(4 + 2 * ri) * Hq * Hq + (size_t)n * Hq + k);
        const float4 c = *(const float4*)(Wr + (size_t)(2 * ri)     * Hq * Hq + (size_t)n * Hq + k);
        const float4 b = *(const float4*)(Wr + (size_t)(5 + 2 * ri) * Hq * Hq + (size_t)n * Hq + k);
        const float4 d = *(const float4*)(Wr + (size_t)(2 * ri + 1) * Hq * Hq + (size_t)n * Hq + k);
        const float4 e = *(const float4*)(Wr + (size_t)(3 * ri)     * Hq * Hq + (size_t)n * Hq + k);
        __half* dstw = g_Wcat + (size_t)ri * Hq * KXn + (size_t)n * KXn;
        __half2* d0 = (__half2*)(dstw + k);
        __half2* d1 = (__half2*)(dstw + Hq + k);
        __half2* d2 = (__half2*)(dstw + 2 * Hq + k);
        d0[0] = __floats2half2_rn(a.x - c.x, a.y - c.y);
        d0[1] = __floats2half2_rn(a.z - c.z, a.w - c.w);
        d1[0] = __floats2half2_rn(b.x - d.x, b.y - d.y);
        d1[1] = __floats2half2_rn(b.z - d.z, b.w - d.w);
        d2[0] = __floats2half2_rn(-e.x, -e.y);
        d2[1] = __floats2half2_rn(-e.z, -e.w);
    } else if (blk < GB_RANK) {
        // ---- transpose w_f -> Wcat slot3 (both groups) ----
        int idx = blk - GB_TRANS;
        int x0 = (idx & 31) * 32, y0 = (idx >> 5) * 32;
        int tx = tid & 31, ty = tid >> 5;
        __shared__ float t[32][33];
        #pragma unroll
        for (int r = 0; r < 32; r += 8)
            t[ty + r][tx] = wf[(size_t)(y0 + ty + r) * Hq + x0 + tx];
        __syncthreads();
        #pragma unroll
        for (int r = 0; r < 32; r += 8) {
            int n = x0 + ty + r, h = y0 + tx;
            __half v = __float2half_rn(t[tx][ty + r]);
            g_Wcat[(size_t)n * KXn + 3 * Hq + h] = v;
            g_Wcat[(size_t)Hq * KXn + (size_t)n * KXn + 3 * Hq + h] = v;
        }
    } else if (blk < GB_GROUP) {
        // ---- rank (per batch b) ----
        int b = blk - GB_RANK;
        int i = tid;
        __shared__ float num[128];
        __shared__ int perm[128];
        __shared__ int validCnt;
        int id = 0; float x = 0.f;
        if (i < 128) {
            id = ids[b * 128 + i];
            x = numbers[b * 128 + i];
            num[i] = x;
        }
        if (i == 0) validCnt = 0;
        __syncthreads();
        if (i < 128) {
            int p = 0;
            #pragma unroll 4
            for (int j = 0; j < 128; j++) {
                float y = num[j];
                p += (y < x) || (y == x && j < i);
            }
            perm[p] = i;
            atomicAdd(&validCnt, (id >= 0) ? 1 : 0);
        }
        __syncthreads();
        if (i < 128) {
            g_perm[b * 128 + i] = perm[i];
            int node = perm[i];
            int prev = (i > 0) ? perm[i - 1] : 0;
            g_runstart[b * 128 + i] = (i == 0) || (num[node] != num[prev]);
        }
        if (i == 0) g_invD[b] = 1.f / (float)max(validCnt - 1, 1);
    } else {
        // ---- group rows by resp_i (parallel scan) ----
        __shared__ int cls[NROWS];
        __shared__ int sc[256];
        __shared__ int tcount[256];
        int t = tid;
        for (int m = t; m < NROWS; m += 256) cls[m] = (resp[m] == 1) ? 1 : 0;
        __syncthreads();
        int c0 = 0;
        #pragma unroll
        for (int k = 0; k < 8; k++) c0 += (cls[t * 8 + k] == 0);
        tcount[t] = c0;
        sc[t] = c0;
        __syncthreads();
        #pragma unroll
        for (int step = 1; step < 256; step <<= 1) {
            int v = (t >= step) ? sc[t - step] : 0;
            __syncthreads();
            sc[t] += v;
            __syncthreads();
        }
        int count0 = sc[255];
        int off0 = sc[t] - tcount[t];
        int start1 = ((count0 + 127) / 128) * 128;
        int total1 = NROWS - count0;
        int totalTiles = (start1 + total1 + 127) / 128;
        for (int m = t; m < NPAD; m += 256) g_rowmap[m] = -1;
        __syncthreads();
        int p0 = off0;
        int p1 = start1 + (t * 8 - off0);
        #pragma unroll
        for (int k = 0; k < 8; k++) {
            int m = t * 8 + k;
            if (cls[m] == 0) { g_rowmap[p0] = m; p0++; }
            else             { g_rowmap[p1] = m; p1++; }
        }
        if (t == 0) { g_meta[0] = start1; g_meta[1] = totalTiles; }
    }
}

// ---------- K_prefix: prefix sums via smem cache (grid (16,8), 128 thr) ------
__global__ void __launch_bounds__(128) k_prefix(const int* __restrict__ resp) {
    int b = blockIdx.x, tid = threadIdx.x;
    int h = blockIdx.y * 128 + tid;
    extern __shared__ float u[];                 // [128 i][128 h]
    __shared__ float alpha_s[128];
    __shared__ int perm_s[128], rs_s[128], resp_s[128];
    alpha_s[tid] = g_alpha[b * 128 + tid];
    perm_s[tid]  = g_perm[b * 128 + tid];
    rs_s[tid]    = g_runstart[b * 128 + tid];
    resp_s[tid]  = resp[b * 128 + tid];
    __syncthreads();
    #pragma unroll 8
    for (int i = 0; i < 128; i++)
        u[i * 128 + tid] = alpha_s[i] *
            __half2float(g_X[(size_t)(b * 128 + i) * KXn + 3 * Hq + h]);
    __syncthreads();
    float T0 = 0.f, T1 = 0.f;
    #pragma unroll 8
    for (int i = 0; i < 128; i++) {
        float uu = u[i * 128 + tid];
        if (resp_s[i]) T1 += uu; else T0 += uu;
    }
    g_T[b][0][h] = T0;
    g_T[b][1][h] = T1;
    float invD = g_invD[b];
    float a0 = 0.f, a1 = 0.f, s0 = 0.f, s1 = 0.f;
    for (int p = 0; p < 128; p++) {
        int i = perm_s[p];
        if (rs_s[p]) { s0 = a0; s1 = a1; }
        float uu = u[i * 128 + tid];
        __half* Xi = g_X + (size_t)(b * 128 + i) * KXn;
        Xi[h]          = __float2half_rn(s0 * invD);
        Xi[Hq + h]     = __float2half_rn(s1 * invD);
        Xi[2 * Hq + h] = __float2half_rn(uu * invD);
        if (resp_s[i]) a1 += uu; else a0 += uu;
    }
}

// ---------- K_const2: C[ri][b][h] via smem-staged T, warp owns 2 h ----------
// grid (64 htiles, 2 ri), 256 threads (8 warps x 2 h = 16 h per block).
// smem: T staged as sT4[cls][b][k4] = 2*16*256 float4 = 128 KB.
__global__ void __launch_bounds__(256) k_const2(
    const float* __restrict__ Wr, const float* __restrict__ b_f)
{
    extern __shared__ float4 sT4[];              // [2*16*256]
    int tid = threadIdx.x;
    const float4* gT4 = (const float4*)&g_T[0][0][0];   // [(b*2+cls)*256 + k4]
    for (int i = tid; i < 2 * 16 * 256; i += 256) {
        int b = i >> 9, cls = (i >> 8) & 1, k4 = i & 255;
        sT4[(cls * 16 + b) * 256 + k4] = gT4[i];
    }
    __syncthreads();

    int wid = tid >> 5, lane = tid & 31;
    int ri = blockIdx.y;
    int h0 = blockIdx.x * 16 + wid * 2;
    int h1 = h0 + 1;
    const float4* w0a = (const float4*)(Wr + (size_t)(2 * ri)     * Hq * Hq + (size_t)h0 * Hq);
    const float4* w1a = (const float4*)(Wr + (size_t)(2 * ri + 1) * Hq * Hq + (size_t)h0 * Hq);
    const float4* w0b = (const float4*)(Wr + (size_t)(2 * ri)     * Hq * Hq + (size_t)h1 * Hq);
    const float4* w1b = (const float4*)(Wr + (size_t)(2 * ri + 1) * Hq * Hq + (size_t)h1 * Hq);

    float acc0[16], acc1[16];
    #pragma unroll
    for (int b = 0; b < 16; b++) { acc0[b] = 0.f; acc1[b] = 0.f; }

    #pragma unroll
    for (int it = 0; it < 8; it++) {
        int k4 = it * 32 + lane;
        float4 a0 = w0a[k4], a1 = w1a[k4];
        float4 c0 = w0b[k4], c1 = w1b[k4];
        #pragma unroll
        for (int b = 0; b < 16; b++) {
            float4 t0 = sT4[b * 256 + k4];               // cls 0
            float4 t1 = sT4[(16 + b) * 256 + k4];        // cls 1
            acc0[b] += a0.x * t0.x + a0.y * t0.y + a0.z * t0.z + a0.w * t0.w
                     + a1.x * t1.x + a1.y * t1.y + a1.z * t1.z + a1.w * t1.w;
            acc1[b] += c0.x * t0.x + c0.y * t0.y + c0.z * t0.z + c0.w * t0.w
                     + c1.x * t1.x + c1.y * t1.y + c1.z * t1.z + c1.w * t1.w;
        }
    }
    #pragma unroll
    for (int b = 0; b < 16; b++) {
        #pragma unroll
        for (int s = 16; s > 0; s >>= 1) {
            acc0[b] += __shfl_xor_sync(0xFFFFFFFFu, acc0[b], s);
            acc1[b] += __shfl_xor_sync(0xFFFFFFFFu, acc1[b], s);
        }
    }
    if (lane == 0) {
        float bf0 = b_f[h0], bf1 = b_f[h1];
        #pragma unroll
        for (int b = 0; b < 16; b++) {
            float inv = g_invD[b];
            g_C[ri][b][h0] = acc0[b] * inv + bf0;
            g_C[ri][b][h1] = acc1[b] * inv + bf1;
        }
    }
}

// ---------------- K5: fp16 mma GEMM (R10 config: BN=128, 4-stage) ------------
#define BK      64
#define NKT     (KXn / BK)       // 64
#define TILE_B  (128 * 128)      // bytes per operand tile

__global__ void __launch_bounds__(256, 1)
k_gemm(float* __restrict__ out) {
    int by = blockIdx.y, bx = blockIdx.x;
    if (by >= g_meta[1]) return;

    extern __shared__ char smc[];
    char* As = smc;                      // [4][TILE_B]
    char* Bs = smc + 4 * TILE_B;
    int* rows_s = (int*)(smc + 8 * TILE_B);

    int tid = threadIdx.x;
    int wid = tid >> 5, lane = tid & 31;
    int g = lane >> 2, t4 = lane & 3;
    int wm = wid & 3, wn = wid >> 2;

    for (int r = tid; r < 128; r += 256) rows_s[r] = g_rowmap[by * 128 + r];
    __syncthreads();

    int ri = (by * 128 >= g_meta[0]) ? 1 : 0;
    const __half* Bbase = g_Wcat + (size_t)ri * Hq * KXn + (size_t)(bx * 128) * KXn;
    const float* Cp = &g_C[ri][0][0];

    int cr[4], cch[4], dsw[4];
    const __half* Asrc[4];
    #pragma unroll
    for (int i = 0; i < 4; i++) {
        int idx = tid + i * 256;
        cr[i] = idx >> 3;
        int chunk = idx & 7;
        cch[i] = chunk * 8;
        dsw[i] = cr[i] * 128 + ((chunk ^ (cr[i] & 7)) << 4);
        int grow = rows_s[cr[i]];
        if (grow < 0) grow = 0;
        Asrc[i] = g_X + (size_t)grow * KXn + cch[i];
    }
    uint32_t asb = smem_u32(As), bsb = smem_u32(Bs);

    auto load_tile = [&](int kt, int slot) {
        int kk = kt * BK;
        #pragma unroll
        for (int i = 0; i < 4; i++) {
            CP16(asb + slot * TILE_B + dsw[i], Asrc[i] + kk);
            CP16(bsb + slot * TILE_B + dsw[i],
                 Bbase + (size_t)cr[i] * KXn + kk + cch[i]);
        }
    };

    int rA0 = wm * 32 + (lane & 15);
    int hiA = lane >> 4;
    int nB  = wn * 64 + (lane & 7) + ((lane >> 4) << 3);
    int hiB = (lane >> 3) & 1;

    float acc[2][8][4];
    #pragma unroll
    for (int mf = 0; mf < 2; mf++)
        #pragma unroll
        for (int nf = 0; nf < 8; nf++)
            #pragma unroll
            for (int q = 0; q < 4; q++) acc[mf][nf][q] = 0.f;

    load_tile(0, 0); CP_COMMIT();
    load_tile(1, 1); CP_COMMIT();
    load_tile(2, 2); CP_COMMIT();

    for (int kt = 0; kt < NKT; kt++) {
        int slot = kt & 3;
        CP_WAIT2();
        __syncthreads();
        if (kt + 3 < NKT) load_tile(kt + 3, (kt + 3) & 3);
        CP_COMMIT();

        uint32_t At = asb + slot * TILE_B;
        uint32_t Bt = bsb + slot * TILE_B;
        #pragma unroll
        for (int k16 = 0; k16 < 4; k16++) {
            int kc = k16 * 2;
            uint32_t a[2][4], b[8][2];
            #pragma unroll
            for (int mf = 0; mf < 2; mf++) {
                int row = rA0 + mf * 16;
                uint32_t ad = At + row * 128 + (((kc + hiA) ^ (row & 7)) << 4);
                ldsm4(a[mf][0], a[mf][1], a[mf][2], a[mf][3], ad);
            }
            #pragma unroll
            for (int np = 0; np < 4; np++) {
                int row = nB + np * 16;
                uint32_t bd = Bt + row * 128 + (((kc + hiB) ^ (row & 7)) << 4);
                ldsm4(b[2 * np][0], b[2 * np][1], b[2 * np + 1][0], b[2 * np + 1][1], bd);
            }
            #pragma unroll
            for (int mf = 0; mf < 2; mf++)
                #pragma unroll
                for (int nf = 0; nf < 8; nf++)
                    mma_f16(acc[mf][nf], a[mf], b[nf]);
        }
    }

    // ---- epilogue: + C[ri][b] (incl b_f), relu, scatter rows ----
    #pragma unroll
    for (int mf = 0; mf < 2; mf++) {
        int m0 = wm * 32 + mf * 16 + g;
        int row0 = rows_s[m0];
        int row1 = rows_s[m0 + 8];
        #pragma unroll
        for (int nf = 0; nf < 8; nf++) {
            int col = bx * 128 + wn * 64 + nf * 8 + t4 * 2;
            if (row0 >= 0) {
                const float* c0 = Cp + (size_t)(row0 >> 7) * Hq + col;
                float2 v;
                v.x = fmaxf(acc[mf][nf][0] + c0[0], 0.f);
                v.y = fmaxf(acc[mf][nf][1] + c0[1], 0.f);
                *(float2*)(out + (size_t)row0 * Hq + col) = v;
            }
            if (row1 >= 0) {
                const float* c1 = Cp + (size_t)(row1 >> 7) * Hq + col;
                float2 v;
                v.x = fmaxf(acc[mf][nf][2] + c1[0], 0.f);
                v.y = fmaxf(acc[mf][nf][3] + c1[1], 0.f);
                *(float2*)(out + (size_t)row1 * Hq + col) = v;
            }
        }
    }
}

#define SMEM_GEMM   (8 * TILE_B + 512)
#define SMEM_PREFIX (128 * 128 * 4)
#define SMEM_CONST  (2 * 16 * 1024 * 4)

// ---------------- launch ----------------
extern "C" void kernel_launch(void* const* d_in, const int* in_sizes, int n_in,
                              void* d_out, int out_size) {
    const float* word_emb  = (const float*)d_in[0];
    const int*   num_ids   = (const int*)  d_in[1];
    const int*   is_resp   = (const int*)  d_in[2];
    const float* numbers   = (const float*)d_in[3];
    const float* w_alpha   = (const float*)d_in[4];
    const float* b_alpha   = (const float*)d_in[5];
    const float* w_f       = (const float*)d_in[6];
    const float* b_f       = (const float*)d_in[7];
    const float* W_r       = (const float*)d_in[8];
    float* out = (float*)d_out;

    k_mega<<<GB_TOTAL, 256>>>(word_emb, num_ids, w_alpha, b_alpha,
                              w_f, W_r, numbers, is_resp);

    cudaFuncSetAttribute(k_prefix, cudaFuncAttributeMaxDynamicSharedMemorySize, SMEM_PREFIX);
    k_prefix<<<dim3(Bq, 8), 128, SMEM_PREFIX>>>(is_resp);

    cudaFuncSetAttribute(k_const2, cudaFuncAttributeMaxDynamicSharedMemorySize, SMEM_CONST);
    k_const2<<<dim3(64, 2), 256, SMEM_CONST>>>(W_r, b_f);

    cudaFuncSetAttribute(k_gemm, cudaFuncAttributeMaxDynamicSharedMemorySize, SMEM_GEMM);
    k_gemm<<<dim3(8, 17), 256, SMEM_GEMM>>>(out);
}